// round 5
// baseline (speedup 1.0000x reference)
#include <cuda_runtime.h>
#include <cuda_bf16.h>
#include <cstdint>
#include <math.h>

#define BATCH 2
#define SEQ   2048
#define DIM   1024
#define HEADS 8
#define MROWS (BATCH*SEQ)
#define EPSLN 1e-5f

typedef __nv_bfloat16  bf16;
typedef __nv_bfloat162 bf162;

// ---------------- scratch (device globals; no allocation allowed) ----------
__device__ float g_q [MROWS*DIM];
__device__ float g_sc[BATCH*SEQ*SEQ];
__device__ float g_h [MROWS*DIM];
__device__ bf16 g_xh [MROWS*DIM], g_xl [MROWS*DIM];
__device__ bf16 g_qh [MROWS*DIM], g_ql [MROWS*DIM];
__device__ bf16 g_qTh[MROWS*DIM], g_qTl[MROWS*DIM];   // [B][D][S]
__device__ bf16 g_ph [BATCH*SEQ*SEQ], g_pl [BATCH*SEQ*SEQ];
__device__ bf16 g_hdh[MROWS*DIM], g_hdl[MROWS*DIM];
__device__ bf16 g_hh [MROWS*DIM], g_hl [MROWS*DIM];
__device__ bf16 g_th [MROWS*DIM], g_tl [MROWS*DIM];
__device__ bf16 g_wiTh[DIM*DIM], g_wiTl[DIM*DIM];
__device__ bf16 g_weTh[DIM*DIM], g_weTl[DIM*DIM];

// ---------------- PTX helpers ----------------------------------------------
__device__ __forceinline__ uint32_t smem_u32(const void* p) {
    uint32_t a;
    asm("{ .reg .u64 t; cvta.to.shared.u64 t, %1; cvt.u32.u64 %0, t; }" : "=r"(a) : "l"(p));
    return a;
}
__device__ __forceinline__ void ldsm4(uint32_t& r0, uint32_t& r1, uint32_t& r2, uint32_t& r3,
                                      uint32_t addr) {
    asm volatile("ldmatrix.sync.aligned.m8n8.x4.shared.b16 {%0,%1,%2,%3}, [%4];"
                 : "=r"(r0), "=r"(r1), "=r"(r2), "=r"(r3) : "r"(addr));
}
__device__ __forceinline__ void mma16816(float* d, const uint32_t* a, const uint32_t* b) {
    asm volatile(
        "mma.sync.aligned.m16n8k16.row.col.f32.bf16.bf16.f32 "
        "{%0,%1,%2,%3}, {%4,%5,%6,%7}, {%8,%9}, {%0,%1,%2,%3};"
        : "+f"(d[0]), "+f"(d[1]), "+f"(d[2]), "+f"(d[3])
        : "r"(a[0]), "r"(a[1]), "r"(a[2]), "r"(a[3]), "r"(b[0]), "r"(b[1]));
}
__device__ __forceinline__ void cp16(uint32_t dst, const void* src) {
    asm volatile("cp.async.cg.shared.global [%0], [%1], 16;" :: "r"(dst), "l"(src));
}
#define CP_COMMIT() asm volatile("cp.async.commit_group;" ::: "memory")
#define CP_WAIT1()  asm volatile("cp.async.wait_group 1;" ::: "memory")

__device__ __forceinline__ void split1(float v, bf16& h, bf16& l) {
    h = __float2bfloat16(v);
    l = __float2bfloat16(v - __bfloat162float(h));
}

// ---------------- HMMA bf16-split GEMM --------------------------------------
// C[M,N](fp32) = A[M,K] * B^T ; A,B given as hi/lo bf16 row-major ([M,K],[N,K]).
// 3 passes: AhBh + AhBl + AlBh accumulated in fp32 registers.
// Pass-major inner loop: each accumulator's reuse distance is 16 independent
// MMAs, so the HMMA RAW latency is fully hidden.
#define BMM 128
#define BNN 128
#define BKK 64
#define KPAD 72                       // elements per smem row (64 + 8 pad)
#define ROWB (KPAD*2)                 // 144 bytes per row
#define ABYTES (128*ROWB)             // 18432 per buffer
#define STAGE  (4*ABYTES)             // Ah,Al,Bh,Bl
#define GEMM_SMEM (2*STAGE)           // 147456

// EPI: 0 fp32 | 1 alpha*fp32 | 2 res-add + split | 3 +bias fp32 | 4 swish+split | 5 fp32+split
// CAUSAL: 0 none | 1 skip tiles above diagonal | 2 clamp K to crow+BMM
template<int EPI, int CAUSAL>
__global__ __launch_bounds__(256, 1)
void hmma_gemm(const bf16* __restrict__ Ah, const bf16* __restrict__ Al,
               const bf16* __restrict__ Bh, const bf16* __restrict__ Bl,
               float* __restrict__ C, bf16* __restrict__ Ch, bf16* __restrict__ Cl,
               const float* __restrict__ res, const float* __restrict__ bias,
               int M, int N, int K, float alpha, long sA, long sB, long sC)
{
    const int crow = blockIdx.y * BMM;
    const int ccol = blockIdx.x * BNN;
    if (CAUSAL == 1 && ccol >= crow + BMM) return;

    const int b = blockIdx.z;
    Ah += (long)b * sA;  Al += (long)b * sA;
    Bh += (long)b * sB;  Bl += (long)b * sB;

    extern __shared__ char smem[];
    const uint32_t sb = smem_u32(smem);
    const int tid  = threadIdx.x;
    const int lane = tid & 31;
    const int wid  = tid >> 5;
    const int wm   = wid & 1;        // 2 m-slices of 64
    const int wn   = wid >> 1;       // 4 n-slices of 32

    const int Keff = (CAUSAL == 2) ? (crow + BMM) : K;
    const int nC = Keff / BKK;

    // cp.async mapping: thread -> (row, 4 contiguous 16B chunks)
    const int r  = tid >> 1;
    const int c0 = (tid & 1) * 4;    // chunk base (each chunk = 8 bf16 = 16B)
    const bf16* pAh = Ah + (long)(crow + r) * K + c0 * 8;
    const bf16* pAl = Al + (long)(crow + r) * K + c0 * 8;
    const bf16* pBh = Bh + (long)(ccol + r) * K + c0 * 8;
    const bf16* pBl = Bl + (long)(ccol + r) * K + c0 * 8;
    const uint32_t dstoff = r * ROWB + c0 * 16;

    // ldmatrix per-thread base addresses (A buffer / Bh buffer)
    const uint32_t aAddr = sb + (wm * 64 + (lane & 15)) * ROWB + (lane >> 4) * 16;
    const uint32_t bAddr = sb + 2 * ABYTES +
                           (wn * 32 + ((lane >> 4) << 3) + (lane & 7)) * ROWB +
                           ((lane >> 3) & 1) * 16;

    float acc[4][4][4];
    #pragma unroll
    for (int i = 0; i < 4; i++)
        #pragma unroll
        for (int j = 0; j < 4; j++)
            #pragma unroll
            for (int k = 0; k < 4; k++) acc[i][j][k] = 0.f;

    // prefetch chunk 0
    {
        const uint32_t st = sb + dstoff;
        #pragma unroll
        for (int i = 0; i < 4; i++) {
            cp16(st + i * 16,              pAh + i * 8);
            cp16(st + ABYTES + i * 16,     pAl + i * 8);
            cp16(st + 2 * ABYTES + i * 16, pBh + i * 8);
            cp16(st + 3 * ABYTES + i * 16, pBl + i * 8);
        }
        CP_COMMIT();
    }

    for (int c = 0; c < nC; c++) {
        if (c + 1 < nC) {
            const uint32_t st = sb + ((c + 1) & 1) * STAGE + dstoff;
            const long ke = (long)(c + 1) * BKK;
            #pragma unroll
            for (int i = 0; i < 4; i++) {
                cp16(st + i * 16,              pAh + ke + i * 8);
                cp16(st + ABYTES + i * 16,     pAl + ke + i * 8);
                cp16(st + 2 * ABYTES + i * 16, pBh + ke + i * 8);
                cp16(st + 3 * ABYTES + i * 16, pBl + ke + i * 8);
            }
        }
        CP_COMMIT();
        CP_WAIT1();
        __syncthreads();

        const uint32_t stg = (c & 1) * STAGE;
        #pragma unroll
        for (int ks = 0; ks < 4; ks++) {
            uint32_t ah[4][4], al[4][4], bh[4][2], bl[4][2];
            #pragma unroll
            for (int mt = 0; mt < 4; mt++) {
                const uint32_t ad = aAddr + stg + mt * (16 * ROWB) + ks * 32;
                ldsm4(ah[mt][0], ah[mt][1], ah[mt][2], ah[mt][3], ad);
                ldsm4(al[mt][0], al[mt][1], al[mt][2], al[mt][3], ad + ABYTES);
            }
            #pragma unroll
            for (int pr = 0; pr < 2; pr++) {
                const uint32_t bd = bAddr + stg + pr * (16 * ROWB) + ks * 32;
                uint32_t r0, r1, r2, r3;
                ldsm4(r0, r1, r2, r3, bd);
                bh[2*pr][0] = r0; bh[2*pr][1] = r1; bh[2*pr+1][0] = r2; bh[2*pr+1][1] = r3;
                ldsm4(r0, r1, r2, r3, bd + ABYTES);
                bl[2*pr][0] = r0; bl[2*pr][1] = r1; bl[2*pr+1][0] = r2; bl[2*pr+1][1] = r3;
            }
            // Pass-major: 16 independent accumulators between reuses.
            #pragma unroll
            for (int mt = 0; mt < 4; mt++)
                #pragma unroll
                for (int nt = 0; nt < 4; nt++)
                    mma16816(acc[mt][nt], ah[mt], bh[nt]);
            #pragma unroll
            for (int mt = 0; mt < 4; mt++)
                #pragma unroll
                for (int nt = 0; nt < 4; nt++)
                    mma16816(acc[mt][nt], ah[mt], bl[nt]);
            #pragma unroll
            for (int mt = 0; mt < 4; mt++)
                #pragma unroll
                for (int nt = 0; nt < 4; nt++)
                    mma16816(acc[mt][nt], al[mt], bh[nt]);
        }
        __syncthreads();
    }

    // ---------------- epilogue ----------------
    const int g  = lane >> 2;
    const int tg = lane & 3;
    #pragma unroll
    for (int mt = 0; mt < 4; mt++)
        #pragma unroll
        for (int nt = 0; nt < 4; nt++)
            #pragma unroll
            for (int hh = 0; hh < 2; hh++) {
                const int row = crow + wm * 64 + mt * 16 + g + hh * 8;
                const int col = ccol + wn * 32 + nt * 8 + tg * 2;
                const long off = (long)b * sC + (long)row * N + col;
                float vx = acc[mt][nt][hh * 2 + 0];
                float vy = acc[mt][nt][hh * 2 + 1];
                if (EPI == 1) { vx *= alpha; vy *= alpha; }
                if (EPI == 2) {
                    const float2 r2 = *reinterpret_cast<const float2*>(res + off);
                    vx += r2.x; vy += r2.y;
                }
                if (EPI == 3) { vx += bias[col]; vy += bias[col + 1]; }
                if (EPI == 4) {
                    vx = vx / (1.f + __expf(-vx));
                    vy = vy / (1.f + __expf(-vy));
                }
                if (EPI == 0 || EPI == 1 || EPI == 3 || EPI == 5) {
                    float2 o; o.x = vx; o.y = vy;
                    *reinterpret_cast<float2*>(C + off) = o;
                }
                if (EPI == 2 || EPI == 4 || EPI == 5) {
                    bf16 h0, l0, h1, l1;
                    split1(vx, h0, l0); split1(vy, h1, l1);
                    bf162 hp; hp.x = h0; hp.y = h1;
                    bf162 lp; lp.x = l0; lp.y = l1;
                    *reinterpret_cast<bf162*>(Ch + off) = hp;
                    *reinterpret_cast<bf162*>(Cl + off) = lp;
                }
            }
}

// ---------------- fp32 -> hi/lo bf16 split ---------------------------------
__global__ __launch_bounds__(256)
void split_f32(const float* __restrict__ in, bf16* __restrict__ oh, bf16* __restrict__ ol)
{
    const long i4 = (long)(blockIdx.x * 256 + threadIdx.x) * 4;
    const float4 v = *reinterpret_cast<const float4*>(in + i4);
    bf16 h0, l0, h1, l1, h2, l2, h3, l3;
    split1(v.x, h0, l0); split1(v.y, h1, l1); split1(v.z, h2, l2); split1(v.w, h3, l3);
    bf162 a; a.x = h0; a.y = h1;  bf162 b; b.x = h2; b.y = h3;
    bf162 c; c.x = l0; c.y = l1;  bf162 d; d.x = l2; d.y = l3;
    *reinterpret_cast<bf162*>(oh + i4)     = a;
    *reinterpret_cast<bf162*>(oh + i4 + 2) = b;
    *reinterpret_cast<bf162*>(ol + i4)     = c;
    *reinterpret_cast<bf162*>(ol + i4 + 2) = d;
}

// ---------------- transpose + split: out[c][r] = in[r][c] -------------------
__global__ __launch_bounds__(256)
void transpose_split(const float* __restrict__ in, bf16* __restrict__ oh, bf16* __restrict__ ol,
                     int R, int Cc, long sIn, long sOut)
{
    __shared__ float tile[32][33];
    const int b = blockIdx.z;
    const int col0 = blockIdx.x * 32, row0 = blockIdx.y * 32;
    const int tx = threadIdx.x, ty = threadIdx.y;
    #pragma unroll
    for (int i = 0; i < 4; i++) {
        const int lr = ty + i * 8;
        tile[lr][tx] = in[(long)b * sIn + (long)(row0 + lr) * Cc + col0 + tx];
    }
    __syncthreads();
    #pragma unroll
    for (int i = 0; i < 4; i++) {
        const int lc = ty + i * 8;
        const float v = tile[tx][lc];
        bf16 h, l; split1(v, h, l);
        const long o = (long)b * sOut + (long)(col0 + lc) * R + row0 + tx;
        oh[o] = h; ol[o] = l;
    }
}

// ---------------- weffT[j][d] = sum_h wout[h*D+d][j], split -----------------
__global__ __launch_bounds__(256)
void reduce_weffT(const float* __restrict__ wout, bf16* __restrict__ oh, bf16* __restrict__ ol)
{
    __shared__ float tile[32][33];
    const int j0 = blockIdx.x * 32, d0 = blockIdx.y * 32;
    const int tx = threadIdx.x, ty = threadIdx.y;
    #pragma unroll
    for (int i = 0; i < 4; i++) {
        const int ld = ty + i * 8;
        float s = 0.f;
        #pragma unroll
        for (int h = 0; h < HEADS; h++)
            s += wout[(long)h * DIM * DIM + (long)(d0 + ld) * DIM + j0 + tx];
        tile[ld][tx] = s;
    }
    __syncthreads();
    #pragma unroll
    for (int i = 0; i < 4; i++) {
        const int lj = ty + i * 8;
        const float v = tile[tx][lj];
        bf16 h, l; split1(v, h, l);
        const long o = (long)(j0 + lj) * DIM + d0 + tx;
        oh[o] = h; ol[o] = l;
    }
}

// ---------------- causal softmax: fp32 scores -> split P --------------------
__global__ __launch_bounds__(256)
void softmax_split(float* __restrict__ sc, bf16* __restrict__ ph, bf16* __restrict__ pl, int S)
{
    const int gr = blockIdx.x;
    const int b = gr / S, i = gr % S;
    float* row = sc + (long)b * S * S + (long)i * S;
    bf16* rh = ph + (long)b * S * S + (long)i * S;
    bf16* rl = pl + (long)b * S * S + (long)i * S;
    const int n = i + 1;
    const int tid = threadIdx.x;
    __shared__ float red[256];

    float m = -3.0e38f;
    for (int j = tid; j < n; j += 256) m = fmaxf(m, row[j]);
    red[tid] = m; __syncthreads();
    for (int s = 128; s > 0; s >>= 1) { if (tid < s) red[tid] = fmaxf(red[tid], red[tid + s]); __syncthreads(); }
    m = red[0]; __syncthreads();

    float sum = 0.f;
    for (int j = tid; j < n; j += 256) { const float e = __expf(row[j] - m); row[j] = e; sum += e; }
    red[tid] = sum; __syncthreads();
    for (int s = 128; s > 0; s >>= 1) { if (tid < s) red[tid] += red[tid + s]; __syncthreads(); }
    const float inv = 1.f / red[0];

    for (int j = tid; j < n; j += 256) {
        const float p = row[j] * inv;
        bf16 h, l; split1(p, h, l);
        rh[j] = h; rl[j] = l;
    }
    const bf16 z = __float2bfloat16(0.f);
    for (int j = n + tid; j < S; j += 256) { rh[j] = z; rl[j] = z; }
}

// ---------------- LayerNorm -> split ----------------------------------------
__global__ __launch_bounds__(256)
void layernorm_split(const float* __restrict__ in, bf16* __restrict__ oh, bf16* __restrict__ ol, int N)
{
    const long r = blockIdx.x;
    const float* x = in + r * N;
    const int tid = threadIdx.x;
    __shared__ float rs[256], rss[256];

    const float4 a = *reinterpret_cast<const float4*>(&x[tid * 4]);
    rs[tid]  = a.x + a.y + a.z + a.w;
    rss[tid] = a.x * a.x + a.y * a.y + a.z * a.z + a.w * a.w;
    __syncthreads();
    for (int k = 128; k > 0; k >>= 1) {
        if (tid < k) { rs[tid] += rs[tid + k]; rss[tid] += rss[tid + k]; }
        __syncthreads();
    }
    const float mean = rs[0] / N;
    const float msq  = rss[0] / N;
    const float rstd = rsqrtf(msq - mean * mean + EPSLN);
    const float v0 = (a.x - mean) * rstd, v1 = (a.y - mean) * rstd;
    const float v2 = (a.z - mean) * rstd, v3 = (a.w - mean) * rstd;
    bf16 h0, l0, h1, l1, h2, l2, h3, l3;
    split1(v0, h0, l0); split1(v1, h1, l1); split1(v2, h2, l2); split1(v3, h3, l3);
    bf162 p0; p0.x = h0; p0.y = h1;
    bf162 p1; p1.x = h2; p1.y = h3;
    bf162 q0; q0.x = l0; q0.y = l1;
    bf162 q1; q1.x = l2; q1.y = l3;
    *reinterpret_cast<bf162*>(oh + r * N + tid * 4)     = p0;
    *reinterpret_cast<bf162*>(oh + r * N + tid * 4 + 2) = p1;
    *reinterpret_cast<bf162*>(ol + r * N + tid * 4)     = q0;
    *reinterpret_cast<bf162*>(ol + r * N + tid * 4 + 2) = q1;
}

// ---------------------------------------------------------------------------
extern "C" void kernel_launch(void* const* d_in, const int* in_sizes, int n_in,
                              void* d_out, int out_size)
{
    const float* x    = (const float*)d_in[0];
    const float* wi   = (const float*)d_in[2];
    const float* wout = (const float*)d_in[3];
    const float* bias = (const float*)d_in[4];
    float* out = (float*)d_out;

    float *q, *sc, *h;
    bf16 *xh, *xl, *qh, *ql, *qTh, *qTl, *ph, *pl, *hdh, *hdl, *hh, *hl, *th, *tl;
    bf16 *wiTh, *wiTl, *weTh, *weTl;
    cudaGetSymbolAddress((void**)&q, g_q);     cudaGetSymbolAddress((void**)&sc, g_sc);
    cudaGetSymbolAddress((void**)&h, g_h);
    cudaGetSymbolAddress((void**)&xh, g_xh);   cudaGetSymbolAddress((void**)&xl, g_xl);
    cudaGetSymbolAddress((void**)&qh, g_qh);   cudaGetSymbolAddress((void**)&ql, g_ql);
    cudaGetSymbolAddress((void**)&qTh, g_qTh); cudaGetSymbolAddress((void**)&qTl, g_qTl);
    cudaGetSymbolAddress((void**)&ph, g_ph);   cudaGetSymbolAddress((void**)&pl, g_pl);
    cudaGetSymbolAddress((void**)&hdh, g_hdh); cudaGetSymbolAddress((void**)&hdl, g_hdl);
    cudaGetSymbolAddress((void**)&hh, g_hh);   cudaGetSymbolAddress((void**)&hl, g_hl);
    cudaGetSymbolAddress((void**)&th, g_th);   cudaGetSymbolAddress((void**)&tl, g_tl);
    cudaGetSymbolAddress((void**)&wiTh, g_wiTh); cudaGetSymbolAddress((void**)&wiTl, g_wiTl);
    cudaGetSymbolAddress((void**)&weTh, g_weTh); cudaGetSymbolAddress((void**)&weTl, g_weTl);

    cudaFuncSetAttribute(hmma_gemm<5,0>, cudaFuncAttributeMaxDynamicSharedMemorySize, GEMM_SMEM);
    cudaFuncSetAttribute(hmma_gemm<1,1>, cudaFuncAttributeMaxDynamicSharedMemorySize, GEMM_SMEM);
    cudaFuncSetAttribute(hmma_gemm<2,2>, cudaFuncAttributeMaxDynamicSharedMemorySize, GEMM_SMEM);
    cudaFuncSetAttribute(hmma_gemm<3,0>, cudaFuncAttributeMaxDynamicSharedMemorySize, GEMM_SMEM);
    cudaFuncSetAttribute(hmma_gemm<4,0>, cudaFuncAttributeMaxDynamicSharedMemorySize, GEMM_SMEM);
    cudaFuncSetAttribute(hmma_gemm<0,0>, cudaFuncAttributeMaxDynamicSharedMemorySize, GEMM_SMEM);

    const int S = SEQ, D = DIM, M = MROWS;
    const float alpha = 1.0f / 32.0f;   // 1/sqrt(1024)
    const long SD = (long)S * D, SS = (long)S * S;

    // prep: weight transposes/splits + x split
    reduce_weffT<<<dim3(32, 32, 1), dim3(32, 8)>>>(wout, weTh, weTl);
    transpose_split<<<dim3(32, 32, 1), dim3(32, 8)>>>(wi, wiTh, wiTl, D, D, 0, 0);
    split_f32<<<M * D / 1024, 256>>>(x, xh, xl);

    // q = x @ wi  (fp32 + splits)
    hmma_gemm<5,0><<<dim3(D/BNN, M/BMM, 1), 256, GEMM_SMEM>>>(
        xh, xl, wiTh, wiTl, q, qh, ql, nullptr, nullptr, M, D, D, 0.f, 0, 0, 0);

    // qT splits (per batch)
    transpose_split<<<dim3(D/32, S/32, BATCH), dim3(32, 8)>>>(q, qTh, qTl, S, D, SD, SD);

    // scores = alpha * q q^T  (causal tiles only)
    hmma_gemm<1,1><<<dim3(S/BNN, S/BMM, BATCH), 256, GEMM_SMEM>>>(
        qh, ql, qh, ql, sc, nullptr, nullptr, nullptr, nullptr, S, S, D, alpha, SD, SD, SS);

    // softmax -> P splits
    softmax_split<<<BATCH * S, 256>>>(sc, ph, pl, S);

    // head = P @ q + q  (splits out; K clamped causally)
    hmma_gemm<2,2><<<dim3(D/BNN, S/BMM, BATCH), 256, GEMM_SMEM>>>(
        ph, pl, qTh, qTl, nullptr, hdh, hdl, q, nullptr, S, D, S, 0.f, SS, SD, SD);

    // h = head @ W_eff + bias  (fp32)
    hmma_gemm<3,0><<<dim3(D/BNN, M/BMM, 1), 256, GEMM_SMEM>>>(
        hdh, hdl, weTh, weTl, h, nullptr, nullptr, nullptr, bias, M, D, D, 0.f, 0, 0, 0);

    // LayerNorm -> splits
    layernorm_split<<<M, 256>>>(h, hh, hl, D);

    // t = swish(h @ wi)  (splits out)
    hmma_gemm<4,0><<<dim3(D/BNN, M/BMM, 1), 256, GEMM_SMEM>>>(
        hh, hl, wiTh, wiTl, nullptr, th, tl, nullptr, nullptr, M, D, D, 0.f, 0, 0, 0);

    // out = t @ wi  (fp32)
    hmma_gemm<0,0><<<dim3(D/BNN, M/BMM, 1), 256, GEMM_SMEM>>>(
        th, tl, wiTh, wiTl, out, nullptr, nullptr, nullptr, nullptr, M, D, D, 0.f, 0, 0, 0);
}

// round 8
// speedup vs baseline: 1.5565x; 1.5565x over previous
#include <cuda_runtime.h>
#include <cuda_bf16.h>
#include <cstdint>
#include <math.h>

#define BATCH 2
#define SEQ   2048
#define DIM   1024
#define HEADS 8
#define MROWS (BATCH*SEQ)
#define EPSLN 1e-5f

typedef __nv_bfloat16  bf16;
typedef __nv_bfloat162 bf162;

// ---------------- scratch (device globals; no allocation allowed) ----------
__device__ float g_q [MROWS*DIM];
__device__ float g_sc[BATCH*SEQ*SEQ];
__device__ float g_h [MROWS*DIM];
__device__ bf16 g_xh [MROWS*DIM], g_xl [MROWS*DIM];
__device__ bf16 g_qh [MROWS*DIM], g_ql [MROWS*DIM];
__device__ bf16 g_qTh[MROWS*DIM], g_qTl[MROWS*DIM];   // [B][D][S]
__device__ bf16 g_ph [BATCH*SEQ*SEQ], g_pl [BATCH*SEQ*SEQ];
__device__ bf16 g_hdh[MROWS*DIM], g_hdl[MROWS*DIM];
__device__ bf16 g_hh [MROWS*DIM], g_hl [MROWS*DIM];
__device__ bf16 g_th [MROWS*DIM], g_tl [MROWS*DIM];
__device__ bf16 g_wiTh[DIM*DIM], g_wiTl[DIM*DIM];
__device__ bf16 g_weTh[DIM*DIM], g_weTl[DIM*DIM];

// ---------------- PTX helpers ----------------------------------------------
__device__ __forceinline__ uint32_t smem_u32(const void* p) {
    uint32_t a;
    asm("{ .reg .u64 t; cvta.to.shared.u64 t, %1; cvt.u32.u64 %0, t; }" : "=r"(a) : "l"(p));
    return a;
}
__device__ __forceinline__ void ldsm4(uint32_t& r0, uint32_t& r1, uint32_t& r2, uint32_t& r3,
                                      uint32_t addr) {
    asm volatile("ldmatrix.sync.aligned.m8n8.x4.shared.b16 {%0,%1,%2,%3}, [%4];"
                 : "=r"(r0), "=r"(r1), "=r"(r2), "=r"(r3) : "r"(addr));
}
__device__ __forceinline__ void mma16816(float* d, const uint32_t* a, const uint32_t* b) {
    asm volatile(
        "mma.sync.aligned.m16n8k16.row.col.f32.bf16.bf16.f32 "
        "{%0,%1,%2,%3}, {%4,%5,%6,%7}, {%8,%9}, {%0,%1,%2,%3};"
        : "+f"(d[0]), "+f"(d[1]), "+f"(d[2]), "+f"(d[3])
        : "r"(a[0]), "r"(a[1]), "r"(a[2]), "r"(a[3]), "r"(b[0]), "r"(b[1]));
}
__device__ __forceinline__ void cp16(uint32_t dst, const void* src) {
    asm volatile("cp.async.cg.shared.global [%0], [%1], 16;" :: "r"(dst), "l"(src));
}
#define CP_COMMIT() asm volatile("cp.async.commit_group;" ::: "memory")
#define CP_WAIT1()  asm volatile("cp.async.wait_group 1;" ::: "memory")

__device__ __forceinline__ void split1(float v, bf16& h, bf16& l) {
    h = __float2bfloat16(v);
    l = __float2bfloat16(v - __bfloat162float(h));
}

// ---------------- HMMA bf16-split GEMM --------------------------------------
// C[M,N](fp32) = A[M,K] * B^T ; A,B given as hi/lo bf16 row-major ([M,K],[N,K]).
// 3 passes: AhBh + AhBl + AlBh accumulated in fp32 registers.
// 3-stage cp.async pipeline, 1 syncthreads/chunk, register fragment
// double-buffering across k16 steps.
#define BMM 128
#define BNN 128
#define BKK 64
#define KPAD 72                       // elements per smem row (64 + 8 pad)
#define ROWB (KPAD*2)                 // 144 bytes per row
#define ABYTES (128*ROWB)             // 18432 per buffer
#define STAGE  (4*ABYTES)             // Ah,Al,Bh,Bl = 73728
#define NSTAGE 3
#define GEMM_SMEM (NSTAGE*STAGE)      // 221184

// EPI: 0 fp32 | 1 alpha*fp32 | 2 res-add + split | 3 +bias fp32 | 4 swish+split | 5 fp32+split
// CAUSAL: 0 none | 1 skip tiles above diagonal | 2 clamp K to crow+BMM
template<int EPI, int CAUSAL>
__global__ __launch_bounds__(256, 1)
void hmma_gemm(const bf16* __restrict__ Ah, const bf16* __restrict__ Al,
               const bf16* __restrict__ Bh, const bf16* __restrict__ Bl,
               float* __restrict__ C, bf16* __restrict__ Ch, bf16* __restrict__ Cl,
               const float* __restrict__ res, const float* __restrict__ bias,
               int M, int N, int K, float alpha, long sA, long sB, long sC)
{
    const int crow = blockIdx.y * BMM;
    const int ccol = blockIdx.x * BNN;
    if (CAUSAL == 1 && ccol >= crow + BMM) return;

    const int b = blockIdx.z;
    Ah += (long)b * sA;  Al += (long)b * sA;
    Bh += (long)b * sB;  Bl += (long)b * sB;

    extern __shared__ char smem[];
    const uint32_t sb = smem_u32(smem);
    const int tid  = threadIdx.x;
    const int lane = tid & 31;
    const int wid  = tid >> 5;
    const int wm   = wid & 1;        // 2 m-slices of 64
    const int wn   = wid >> 1;       // 4 n-slices of 32

    const int Keff = (CAUSAL == 2) ? (crow + BMM) : K;
    const int nC = Keff / BKK;

    // cp.async mapping: thread -> (row, 4 contiguous 16B chunks)
    const int r  = tid >> 1;
    const int c0 = (tid & 1) * 4;    // chunk base (each chunk = 8 bf16 = 16B)
    const bf16* pAh = Ah + (long)(crow + r) * K + c0 * 8;
    const bf16* pAl = Al + (long)(crow + r) * K + c0 * 8;
    const bf16* pBh = Bh + (long)(ccol + r) * K + c0 * 8;
    const bf16* pBl = Bl + (long)(ccol + r) * K + c0 * 8;
    const uint32_t dstoff = r * ROWB + c0 * 16;

    // ldmatrix per-thread base addresses (A buffer / Bh buffer)
    const uint32_t aAddr = sb + (wm * 64 + (lane & 15)) * ROWB + (lane >> 4) * 16;
    const uint32_t bAddr = sb + 2 * ABYTES +
                           (wn * 32 + ((lane >> 4) << 3) + (lane & 7)) * ROWB +
                           ((lane >> 3) & 1) * 16;

    float acc[4][4][4];
    #pragma unroll
    for (int i = 0; i < 4; i++)
        #pragma unroll
        for (int j = 0; j < 4; j++)
            #pragma unroll
            for (int k = 0; k < 4; k++) acc[i][j][k] = 0.f;

    // prologue: prefetch chunks 0 and 1 into stages 0, 1
    #pragma unroll
    for (int pc = 0; pc < 2; pc++) {
        if (pc < nC) {
            const uint32_t st = sb + pc * STAGE + dstoff;
            const long ke = (long)pc * BKK;
            #pragma unroll
            for (int i = 0; i < 4; i++) {
                cp16(st + i * 16,              pAh + ke + i * 8);
                cp16(st + ABYTES + i * 16,     pAl + ke + i * 8);
                cp16(st + 2 * ABYTES + i * 16, pBh + ke + i * 8);
                cp16(st + 3 * ABYTES + i * 16, pBl + ke + i * 8);
            }
        }
        CP_COMMIT();
    }

    uint32_t ah[2][4][4], al[2][4][4], bh[2][4][2], bl[2][4][2];

#define LOAD_FRAGS(buf, stg, kss) do {                                          \
    _Pragma("unroll")                                                           \
    for (int mt = 0; mt < 4; mt++) {                                            \
        const uint32_t ad = aAddr + (stg) + mt * (16 * ROWB) + (kss) * 32;      \
        ldsm4(ah[buf][mt][0], ah[buf][mt][1], ah[buf][mt][2], ah[buf][mt][3], ad); \
        ldsm4(al[buf][mt][0], al[buf][mt][1], al[buf][mt][2], al[buf][mt][3], ad + ABYTES); \
    }                                                                           \
    _Pragma("unroll")                                                           \
    for (int pr = 0; pr < 2; pr++) {                                            \
        const uint32_t bd = bAddr + (stg) + pr * (16 * ROWB) + (kss) * 32;      \
        uint32_t r0, r1, r2, r3;                                                \
        ldsm4(r0, r1, r2, r3, bd);                                              \
        bh[buf][2*pr][0] = r0; bh[buf][2*pr][1] = r1;                           \
        bh[buf][2*pr+1][0] = r2; bh[buf][2*pr+1][1] = r3;                       \
        ldsm4(r0, r1, r2, r3, bd + ABYTES);                                     \
        bl[buf][2*pr][0] = r0; bl[buf][2*pr][1] = r1;                           \
        bl[buf][2*pr+1][0] = r2; bl[buf][2*pr+1][1] = r3;                       \
    }                                                                           \
} while (0)

    for (int c = 0; c < nC; c++) {
        CP_WAIT1();          // chunk c's data resident
        __syncthreads();     // publish it; also proves stage (c+2)%3 is free

        // prefetch chunk c+2 into stage (c+2)%3
        if (c + 2 < nC) {
            const uint32_t st = sb + ((c + 2) % NSTAGE) * STAGE + dstoff;
            const long ke = (long)(c + 2) * BKK;
            #pragma unroll
            for (int i = 0; i < 4; i++) {
                cp16(st + i * 16,              pAh + ke + i * 8);
                cp16(st + ABYTES + i * 16,     pAl + ke + i * 8);
                cp16(st + 2 * ABYTES + i * 16, pBh + ke + i * 8);
                cp16(st + 3 * ABYTES + i * 16, pBl + ke + i * 8);
            }
        }
        CP_COMMIT();

        const uint32_t stg = (c % NSTAGE) * STAGE;
        LOAD_FRAGS(0, stg, 0);
        #pragma unroll
        for (int ks = 0; ks < 4; ks++) {
            const int cur = ks & 1;
            if (ks < 3) LOAD_FRAGS(cur ^ 1, stg, ks + 1);
            #pragma unroll
            for (int mt = 0; mt < 4; mt++)
                #pragma unroll
                for (int nt = 0; nt < 4; nt++) {
                    mma16816(acc[mt][nt], ah[cur][mt], bh[cur][nt]);
                    mma16816(acc[mt][nt], ah[cur][mt], bl[cur][nt]);
                    mma16816(acc[mt][nt], al[cur][mt], bh[cur][nt]);
                }
        }
    }
#undef LOAD_FRAGS

    // ---------------- epilogue ----------------
    const int g  = lane >> 2;
    const int tg = lane & 3;
    #pragma unroll
    for (int mt = 0; mt < 4; mt++)
        #pragma unroll
        for (int nt = 0; nt < 4; nt++)
            #pragma unroll
            for (int hh = 0; hh < 2; hh++) {
                const int row = crow + wm * 64 + mt * 16 + g + hh * 8;
                const int col = ccol + wn * 32 + nt * 8 + tg * 2;
                const long off = (long)b * sC + (long)row * N + col;
                float vx = acc[mt][nt][hh * 2 + 0];
                float vy = acc[mt][nt][hh * 2 + 1];
                if (EPI == 1) { vx *= alpha; vy *= alpha; }
                if (EPI == 2) {
                    const float2 r2 = *reinterpret_cast<const float2*>(res + off);
                    vx += r2.x; vy += r2.y;
                }
                if (EPI == 3) { vx += bias[col]; vy += bias[col + 1]; }
                if (EPI == 4) {
                    vx = vx / (1.f + __expf(-vx));
                    vy = vy / (1.f + __expf(-vy));
                }
                if (EPI == 0 || EPI == 1 || EPI == 3 || EPI == 5) {
                    float2 o; o.x = vx; o.y = vy;
                    *reinterpret_cast<float2*>(C + off) = o;
                }
                if (EPI == 2 || EPI == 4 || EPI == 5) {
                    bf16 h0, l0, h1, l1;
                    split1(vx, h0, l0); split1(vy, h1, l1);
                    bf162 hp; hp.x = h0; hp.y = h1;
                    bf162 lp; lp.x = l0; lp.y = l1;
                    *reinterpret_cast<bf162*>(Ch + off) = hp;
                    *reinterpret_cast<bf162*>(Cl + off) = lp;
                }
            }
}

// ---------------- fp32 -> hi/lo bf16 split ---------------------------------
__global__ __launch_bounds__(256)
void split_f32(const float* __restrict__ in, bf16* __restrict__ oh, bf16* __restrict__ ol)
{
    const long i4 = (long)(blockIdx.x * 256 + threadIdx.x) * 4;
    const float4 v = *reinterpret_cast<const float4*>(in + i4);
    bf16 h0, l0, h1, l1, h2, l2, h3, l3;
    split1(v.x, h0, l0); split1(v.y, h1, l1); split1(v.z, h2, l2); split1(v.w, h3, l3);
    bf162 a; a.x = h0; a.y = h1;  bf162 b; b.x = h2; b.y = h3;
    bf162 c; c.x = l0; c.y = l1;  bf162 d; d.x = l2; d.y = l3;
    *reinterpret_cast<bf162*>(oh + i4)     = a;
    *reinterpret_cast<bf162*>(oh + i4 + 2) = b;
    *reinterpret_cast<bf162*>(ol + i4)     = c;
    *reinterpret_cast<bf162*>(ol + i4 + 2) = d;
}

// ---------------- transpose + split: out[c][r] = in[r][c] -------------------
__global__ __launch_bounds__(256)
void transpose_split(const float* __restrict__ in, bf16* __restrict__ oh, bf16* __restrict__ ol,
                     int R, int Cc, long sIn, long sOut)
{
    __shared__ float tile[32][33];
    const int b = blockIdx.z;
    const int col0 = blockIdx.x * 32, row0 = blockIdx.y * 32;
    const int tx = threadIdx.x, ty = threadIdx.y;
    #pragma unroll
    for (int i = 0; i < 4; i++) {
        const int lr = ty + i * 8;
        tile[lr][tx] = in[(long)b * sIn + (long)(row0 + lr) * Cc + col0 + tx];
    }
    __syncthreads();
    #pragma unroll
    for (int i = 0; i < 4; i++) {
        const int lc = ty + i * 8;
        const float v = tile[tx][lc];
        bf16 h, l; split1(v, h, l);
        const long o = (long)b * sOut + (long)(col0 + lc) * R + row0 + tx;
        oh[o] = h; ol[o] = l;
    }
}

// ---------------- weffT[j][d] = sum_h wout[h*D+d][j], split -----------------
__global__ __launch_bounds__(256)
void reduce_weffT(const float* __restrict__ wout, bf16* __restrict__ oh, bf16* __restrict__ ol)
{
    __shared__ float tile[32][33];
    const int j0 = blockIdx.x * 32, d0 = blockIdx.y * 32;
    const int tx = threadIdx.x, ty = threadIdx.y;
    #pragma unroll
    for (int i = 0; i < 4; i++) {
        const int ld = ty + i * 8;
        float s = 0.f;
        #pragma unroll
        for (int h = 0; h < HEADS; h++)
            s += wout[(long)h * DIM * DIM + (long)(d0 + ld) * DIM + j0 + tx];
        tile[ld][tx] = s;
    }
    __syncthreads();
    #pragma unroll
    for (int i = 0; i < 4; i++) {
        const int lj = ty + i * 8;
        const float v = tile[tx][lj];
        bf16 h, l; split1(v, h, l);
        const long o = (long)(j0 + lj) * DIM + d0 + tx;
        oh[o] = h; ol[o] = l;
    }
}

// ---------------- causal softmax: fp32 scores -> split P --------------------
__global__ __launch_bounds__(256)
void softmax_split(float* __restrict__ sc, bf16* __restrict__ ph, bf16* __restrict__ pl, int S)
{
    const int gr = blockIdx.x;
    const int b = gr / S, i = gr % S;
    float* row = sc + (long)b * S * S + (long)i * S;
    bf16* rh = ph + (long)b * S * S + (long)i * S;
    bf16* rl = pl + (long)b * S * S + (long)i * S;
    const int n = i + 1;
    const int tid = threadIdx.x;
    __shared__ float red[256];

    float m = -3.0e38f;
    for (int j = tid; j < n; j += 256) m = fmaxf(m, row[j]);
    red[tid] = m; __syncthreads();
    for (int s = 128; s > 0; s >>= 1) { if (tid < s) red[tid] = fmaxf(red[tid], red[tid + s]); __syncthreads(); }
    m = red[0]; __syncthreads();

    float sum = 0.f;
    for (int j = tid; j < n; j += 256) { const float e = __expf(row[j] - m); row[j] = e; sum += e; }
    red[tid] = sum; __syncthreads();
    for (int s = 128; s > 0; s >>= 1) { if (tid < s) red[tid] += red[tid + s]; __syncthreads(); }
    const float inv = 1.f / red[0];

    for (int j = tid; j < n; j += 256) {
        const float p = row[j] * inv;
        bf16 h, l; split1(p, h, l);
        rh[j] = h; rl[j] = l;
    }
    const bf16 z = __float2bfloat16(0.f);
    for (int j = n + tid; j < S; j += 256) { rh[j] = z; rl[j] = z; }
}

// ---------------- LayerNorm -> split ----------------------------------------
__global__ __launch_bounds__(256)
void layernorm_split(const float* __restrict__ in, bf16* __restrict__ oh, bf16* __restrict__ ol, int N)
{
    const long r = blockIdx.x;
    const float* x = in + r * N;
    const int tid = threadIdx.x;
    __shared__ float rs[256], rss[256];

    const float4 a = *reinterpret_cast<const float4*>(&x[tid * 4]);
    rs[tid]  = a.x + a.y + a.z + a.w;
    rss[tid] = a.x * a.x + a.y * a.y + a.z * a.z + a.w * a.w;
    __syncthreads();
    for (int k = 128; k > 0; k >>= 1) {
        if (tid < k) { rs[tid] += rs[tid + k]; rss[tid] += rss[tid + k]; }
        __syncthreads();
    }
    const float mean = rs[0] / N;
    const float msq  = rss[0] / N;
    const float rstd = rsqrtf(msq - mean * mean + EPSLN);
    const float v0 = (a.x - mean) * rstd, v1 = (a.y - mean) * rstd;
    const float v2 = (a.z - mean) * rstd, v3 = (a.w - mean) * rstd;
    bf16 h0, l0, h1, l1, h2, l2, h3, l3;
    split1(v0, h0, l0); split1(v1, h1, l1); split1(v2, h2, l2); split1(v3, h3, l3);
    bf162 p0; p0.x = h0; p0.y = h1;
    bf162 p1; p1.x = h2; p1.y = h3;
    bf162 q0; q0.x = l0; q0.y = l1;
    bf162 q1; q1.x = l2; q1.y = l3;
    *reinterpret_cast<bf162*>(oh + r * N + tid * 4)     = p0;
    *reinterpret_cast<bf162*>(oh + r * N + tid * 4 + 2) = p1;
    *reinterpret_cast<bf162*>(ol + r * N + tid * 4)     = q0;
    *reinterpret_cast<bf162*>(ol + r * N + tid * 4 + 2) = q1;
}

// ---------------------------------------------------------------------------
extern "C" void kernel_launch(void* const* d_in, const int* in_sizes, int n_in,
                              void* d_out, int out_size)
{
    const float* x    = (const float*)d_in[0];
    const float* wi   = (const float*)d_in[2];
    const float* wout = (const float*)d_in[3];
    const float* bias = (const float*)d_in[4];
    float* out = (float*)d_out;

    float *q, *sc, *h;
    bf16 *xh, *xl, *qh, *ql, *qTh, *qTl, *ph, *pl, *hdh, *hdl, *hh, *hl, *th, *tl;
    bf16 *wiTh, *wiTl, *weTh, *weTl;
    cudaGetSymbolAddress((void**)&q, g_q);     cudaGetSymbolAddress((void**)&sc, g_sc);
    cudaGetSymbolAddress((void**)&h, g_h);
    cudaGetSymbolAddress((void**)&xh, g_xh);   cudaGetSymbolAddress((void**)&xl, g_xl);
    cudaGetSymbolAddress((void**)&qh, g_qh);   cudaGetSymbolAddress((void**)&ql, g_ql);
    cudaGetSymbolAddress((void**)&qTh, g_qTh); cudaGetSymbolAddress((void**)&qTl, g_qTl);
    cudaGetSymbolAddress((void**)&ph, g_ph);   cudaGetSymbolAddress((void**)&pl, g_pl);
    cudaGetSymbolAddress((void**)&hdh, g_hdh); cudaGetSymbolAddress((void**)&hdl, g_hdl);
    cudaGetSymbolAddress((void**)&hh, g_hh);   cudaGetSymbolAddress((void**)&hl, g_hl);
    cudaGetSymbolAddress((void**)&th, g_th);   cudaGetSymbolAddress((void**)&tl, g_tl);
    cudaGetSymbolAddress((void**)&wiTh, g_wiTh); cudaGetSymbolAddress((void**)&wiTl, g_wiTl);
    cudaGetSymbolAddress((void**)&weTh, g_weTh); cudaGetSymbolAddress((void**)&weTl, g_weTl);

    cudaFuncSetAttribute(hmma_gemm<5,0>, cudaFuncAttributeMaxDynamicSharedMemorySize, GEMM_SMEM);
    cudaFuncSetAttribute(hmma_gemm<1,1>, cudaFuncAttributeMaxDynamicSharedMemorySize, GEMM_SMEM);
    cudaFuncSetAttribute(hmma_gemm<2,2>, cudaFuncAttributeMaxDynamicSharedMemorySize, GEMM_SMEM);
    cudaFuncSetAttribute(hmma_gemm<3,0>, cudaFuncAttributeMaxDynamicSharedMemorySize, GEMM_SMEM);
    cudaFuncSetAttribute(hmma_gemm<4,0>, cudaFuncAttributeMaxDynamicSharedMemorySize, GEMM_SMEM);
    cudaFuncSetAttribute(hmma_gemm<0,0>, cudaFuncAttributeMaxDynamicSharedMemorySize, GEMM_SMEM);

    const int S = SEQ, D = DIM, M = MROWS;
    const float alpha = 1.0f / 32.0f;   // 1/sqrt(1024)
    const long SD = (long)S * D, SS = (long)S * S;

    // prep: weight transposes/splits + x split
    reduce_weffT<<<dim3(32, 32, 1), dim3(32, 8)>>>(wout, weTh, weTl);
    transpose_split<<<dim3(32, 32, 1), dim3(32, 8)>>>(wi, wiTh, wiTl, D, D, 0, 0);
    split_f32<<<M * D / 1024, 256>>>(x, xh, xl);

    // q = x @ wi  (fp32 + splits)
    hmma_gemm<5,0><<<dim3(D/BNN, M/BMM, 1), 256, GEMM_SMEM>>>(
        xh, xl, wiTh, wiTl, q, qh, ql, nullptr, nullptr, M, D, D, 0.f, 0, 0, 0);

    // qT splits (per batch)
    transpose_split<<<dim3(D/32, S/32, BATCH), dim3(32, 8)>>>(q, qTh, qTl, S, D, SD, SD);

    // scores = alpha * q q^T  (causal tiles only)
    hmma_gemm<1,1><<<dim3(S/BNN, S/BMM, BATCH), 256, GEMM_SMEM>>>(
        qh, ql, qh, ql, sc, nullptr, nullptr, nullptr, nullptr, S, S, D, alpha, SD, SD, SS);

    // softmax -> P splits
    softmax_split<<<BATCH * S, 256>>>(sc, ph, pl, S);

    // head = P @ q + q  (splits out; K clamped causally)
    hmma_gemm<2,2><<<dim3(D/BNN, S/BMM, BATCH), 256, GEMM_SMEM>>>(
        ph, pl, qTh, qTl, nullptr, hdh, hdl, q, nullptr, S, D, S, 0.f, SS, SD, SD);

    // h = head @ W_eff + bias  (fp32)
    hmma_gemm<3,0><<<dim3(D/BNN, M/BMM, 1), 256, GEMM_SMEM>>>(
        hdh, hdl, weTh, weTl, h, nullptr, nullptr, nullptr, bias, M, D, D, 0.f, 0, 0, 0);

    // LayerNorm -> splits
    layernorm_split<<<M, 256>>>(h, hh, hl, D);

    // t = swish(h @ wi)  (splits out)
    hmma_gemm<4,0><<<dim3(D/BNN, M/BMM, 1), 256, GEMM_SMEM>>>(
        hh, hl, wiTh, wiTl, nullptr, th, tl, nullptr, nullptr, M, D, D, 0.f, 0, 0, 0);

    // out = t @ wi  (fp32)
    hmma_gemm<0,0><<<dim3(D/BNN, M/BMM, 1), 256, GEMM_SMEM>>>(
        th, tl, wiTh, wiTl, out, nullptr, nullptr, nullptr, nullptr, M, D, D, 0.f, 0, 0, 0);
}

// round 11
// speedup vs baseline: 1.8615x; 1.1959x over previous
#include <cuda_runtime.h>
#include <cuda_fp16.h>
#include <cstdint>
#include <math.h>

#define BATCH 2
#define SEQ   2048
#define DIM   1024
#define HEADS 8
#define MROWS (BATCH*SEQ)
#define EPSLN 1e-5f

typedef __half  f16;
typedef __half2 f162;

// ---------------- scratch (device globals; no allocation allowed) ----------
__device__ float g_q [MROWS*DIM];
__device__ float g_sc[BATCH*SEQ*SEQ];
__device__ float g_h [MROWS*DIM];
__device__ f16 g_xh [MROWS*DIM], g_xl [MROWS*DIM];
__device__ f16 g_qh [MROWS*DIM], g_ql [MROWS*DIM];
__device__ f16 g_qTh[MROWS*DIM], g_qTl[MROWS*DIM];   // [B][D][S]
__device__ f16 g_ph [BATCH*SEQ*SEQ], g_pl [BATCH*SEQ*SEQ];
__device__ f16 g_hdh[MROWS*DIM], g_hdl[MROWS*DIM];
__device__ f16 g_hh [MROWS*DIM], g_hl [MROWS*DIM];
__device__ f16 g_th [MROWS*DIM], g_tl [MROWS*DIM];
__device__ f16 g_wiTh[DIM*DIM], g_wiTl[DIM*DIM];
__device__ f16 g_weTh[DIM*DIM], g_weTl[DIM*DIM];

// ---------------- PTX helpers ----------------------------------------------
__device__ __forceinline__ uint32_t smem_u32(const void* p) {
    uint32_t a;
    asm("{ .reg .u64 t; cvta.to.shared.u64 t, %1; cvt.u32.u64 %0, t; }" : "=r"(a) : "l"(p));
    return a;
}
__device__ __forceinline__ void ldsm4(uint32_t& r0, uint32_t& r1, uint32_t& r2, uint32_t& r3,
                                      uint32_t addr) {
    asm volatile("ldmatrix.sync.aligned.m8n8.x4.shared.b16 {%0,%1,%2,%3}, [%4];"
                 : "=r"(r0), "=r"(r1), "=r"(r2), "=r"(r3) : "r"(addr));
}
__device__ __forceinline__ void mma16816(float* d, const uint32_t* a, const uint32_t* b) {
    asm volatile(
        "mma.sync.aligned.m16n8k16.row.col.f32.f16.f16.f32 "
        "{%0,%1,%2,%3}, {%4,%5,%6,%7}, {%8,%9}, {%0,%1,%2,%3};"
        : "+f"(d[0]), "+f"(d[1]), "+f"(d[2]), "+f"(d[3])
        : "r"(a[0]), "r"(a[1]), "r"(a[2]), "r"(a[3]), "r"(b[0]), "r"(b[1]));
}
__device__ __forceinline__ void cp16(uint32_t dst, const void* src) {
    asm volatile("cp.async.cg.shared.global [%0], [%1], 16;" :: "r"(dst), "l"(src));
}
#define CP_COMMIT() asm volatile("cp.async.commit_group;" ::: "memory")
#define CP_WAIT1()  asm volatile("cp.async.wait_group 1;" ::: "memory")

__device__ __forceinline__ void split1(float v, f16& h, f16& l) {
    h = __float2half(v);
    l = __float2half(v - __half2float(h));
}

// ---------------- HMMA fp16-split GEMM --------------------------------------
// C[M,N](fp32) = A[M,K] * B^T ; A split hi/lo fp16, B hi (+lo if NPASS==3).
// NPASS==2: AhBh + AlBh   (B truncation error ~2^-12 relative)
// NPASS==3: AhBh + AhBl + AlBh  (error ~2^-22)
#define BMM 128
#define BNN 128
#define BKK 64
#define KPAD 72                       // elements per smem row (64 + 8 pad)
#define ROWB (KPAD*2)                 // 144 bytes per row
#define ABYTES (128*ROWB)             // 18432 per buffer
#define STAGE  (4*ABYTES)             // Ah,Al,Bh,Bl = 73728
#define NSTAGE 3
#define GEMM_SMEM (NSTAGE*STAGE)      // 221184

// EPI: 0 fp32 | 1 alpha*fp32 | 2 res-add + split | 3 +bias fp32 | 4 swish+split | 5 fp32+split
// CAUSAL: 0 none | 1 skip tiles above diagonal | 2 clamp K to crow+BMM
template<int EPI, int CAUSAL, int NPASS>
__global__ __launch_bounds__(256, 1)
void hmma_gemm(const f16* __restrict__ Ah, const f16* __restrict__ Al,
               const f16* __restrict__ Bh, const f16* __restrict__ Bl,
               float* __restrict__ C, f16* __restrict__ Ch, f16* __restrict__ Cl,
               const float* __restrict__ res, const float* __restrict__ bias,
               int M, int N, int K, float alpha, long sA, long sB, long sC)
{
    const int crow = blockIdx.y * BMM;
    const int ccol = blockIdx.x * BNN;
    if (CAUSAL == 1 && ccol >= crow + BMM) return;

    const int b = blockIdx.z;
    Ah += (long)b * sA;  Al += (long)b * sA;
    Bh += (long)b * sB;
    if (NPASS == 3) Bl += (long)b * sB;

    extern __shared__ char smem[];
    const uint32_t sb = smem_u32(smem);
    const int tid  = threadIdx.x;
    const int lane = tid & 31;
    const int wid  = tid >> 5;
    const int wm   = wid & 1;        // 2 m-slices of 64
    const int wn   = wid >> 1;       // 4 n-slices of 32

    const int Keff = (CAUSAL == 2) ? (crow + BMM) : K;
    const int nC = Keff / BKK;

    // cp.async mapping: thread -> (row, 4 contiguous 16B chunks)
    const int r  = tid >> 1;
    const int c0 = (tid & 1) * 4;
    const f16* pAh = Ah + (long)(crow + r) * K + c0 * 8;
    const f16* pAl = Al + (long)(crow + r) * K + c0 * 8;
    const f16* pBh = Bh + (long)(ccol + r) * K + c0 * 8;
    const f16* pBl = (NPASS == 3) ? (Bl + (long)(ccol + r) * K + c0 * 8) : nullptr;
    const uint32_t dstoff = r * ROWB + c0 * 16;

    // ldmatrix per-thread base addresses
    const uint32_t aAddr = sb + (wm * 64 + (lane & 15)) * ROWB + (lane >> 4) * 16;
    const uint32_t bAddr = sb + 2 * ABYTES +
                           (wn * 32 + ((lane >> 4) << 3) + (lane & 7)) * ROWB +
                           ((lane >> 3) & 1) * 16;

    float acc[4][4][4];
    #pragma unroll
    for (int i = 0; i < 4; i++)
        #pragma unroll
        for (int j = 0; j < 4; j++)
            #pragma unroll
            for (int k = 0; k < 4; k++) acc[i][j][k] = 0.f;

    // prologue: prefetch chunks 0 and 1 into stages 0, 1
    #pragma unroll
    for (int pc = 0; pc < 2; pc++) {
        if (pc < nC) {
            const uint32_t st = sb + pc * STAGE + dstoff;
            const long ke = (long)pc * BKK;
            #pragma unroll
            for (int i = 0; i < 4; i++) {
                cp16(st + i * 16,              pAh + ke + i * 8);
                cp16(st + ABYTES + i * 16,     pAl + ke + i * 8);
                cp16(st + 2 * ABYTES + i * 16, pBh + ke + i * 8);
                if (NPASS == 3) cp16(st + 3 * ABYTES + i * 16, pBl + ke + i * 8);
            }
        }
        CP_COMMIT();
    }

    uint32_t ah[2][4][4], al[2][4][4], bh[2][4][2], bl[2][4][2];

#define LOAD_FRAGS(buf, stg, kss) do {                                          \
    _Pragma("unroll")                                                           \
    for (int mt = 0; mt < 4; mt++) {                                            \
        const uint32_t ad = aAddr + (stg) + mt * (16 * ROWB) + (kss) * 32;      \
        ldsm4(ah[buf][mt][0], ah[buf][mt][1], ah[buf][mt][2], ah[buf][mt][3], ad); \
        ldsm4(al[buf][mt][0], al[buf][mt][1], al[buf][mt][2], al[buf][mt][3], ad + ABYTES); \
    }                                                                           \
    _Pragma("unroll")                                                           \
    for (int pr = 0; pr < 2; pr++) {                                            \
        const uint32_t bd = bAddr + (stg) + pr * (16 * ROWB) + (kss) * 32;      \
        uint32_t r0, r1, r2, r3;                                                \
        ldsm4(r0, r1, r2, r3, bd);                                              \
        bh[buf][2*pr][0] = r0; bh[buf][2*pr][1] = r1;                           \
        bh[buf][2*pr+1][0] = r2; bh[buf][2*pr+1][1] = r3;                       \
        if (NPASS == 3) {                                                       \
            ldsm4(r0, r1, r2, r3, bd + ABYTES);                                 \
            bl[buf][2*pr][0] = r0; bl[buf][2*pr][1] = r1;                       \
            bl[buf][2*pr+1][0] = r2; bl[buf][2*pr+1][1] = r3;                   \
        }                                                                       \
    }                                                                           \
} while (0)

    for (int c = 0; c < nC; c++) {
        CP_WAIT1();
        __syncthreads();

        if (c + 2 < nC) {
            const uint32_t st = sb + ((c + 2) % NSTAGE) * STAGE + dstoff;
            const long ke = (long)(c + 2) * BKK;
            #pragma unroll
            for (int i = 0; i < 4; i++) {
                cp16(st + i * 16,              pAh + ke + i * 8);
                cp16(st + ABYTES + i * 16,     pAl + ke + i * 8);
                cp16(st + 2 * ABYTES + i * 16, pBh + ke + i * 8);
                if (NPASS == 3) cp16(st + 3 * ABYTES + i * 16, pBl + ke + i * 8);
            }
        }
        CP_COMMIT();

        const uint32_t stg = (c % NSTAGE) * STAGE;
        LOAD_FRAGS(0, stg, 0);
        #pragma unroll
        for (int ks = 0; ks < 4; ks++) {
            const int cur = ks & 1;
            if (ks < 3) LOAD_FRAGS(cur ^ 1, stg, ks + 1);
            #pragma unroll
            for (int mt = 0; mt < 4; mt++)
                #pragma unroll
                for (int nt = 0; nt < 4; nt++)
                    mma16816(acc[mt][nt], ah[cur][mt], bh[cur][nt]);
            #pragma unroll
            for (int mt = 0; mt < 4; mt++)
                #pragma unroll
                for (int nt = 0; nt < 4; nt++)
                    mma16816(acc[mt][nt], al[cur][mt], bh[cur][nt]);
            if (NPASS == 3) {
                #pragma unroll
                for (int mt = 0; mt < 4; mt++)
                    #pragma unroll
                    for (int nt = 0; nt < 4; nt++)
                        mma16816(acc[mt][nt], ah[cur][mt], bl[cur][nt]);
            }
        }
    }
#undef LOAD_FRAGS

    // ---------------- epilogue ----------------
    const int g  = lane >> 2;
    const int tg = lane & 3;
    #pragma unroll
    for (int mt = 0; mt < 4; mt++)
        #pragma unroll
        for (int nt = 0; nt < 4; nt++)
            #pragma unroll
            for (int hh = 0; hh < 2; hh++) {
                const int row = crow + wm * 64 + mt * 16 + g + hh * 8;
                const int col = ccol + wn * 32 + nt * 8 + tg * 2;
                const long off = (long)b * sC + (long)row * N + col;
                float vx = acc[mt][nt][hh * 2 + 0];
                float vy = acc[mt][nt][hh * 2 + 1];
                if (EPI == 1) { vx *= alpha; vy *= alpha; }
                if (EPI == 2) {
                    const float2 r2 = *reinterpret_cast<const float2*>(res + off);
                    vx += r2.x; vy += r2.y;
                }
                if (EPI == 3) { vx += bias[col]; vy += bias[col + 1]; }
                if (EPI == 4) {
                    vx = vx / (1.f + __expf(-vx));
                    vy = vy / (1.f + __expf(-vy));
                }
                if (EPI == 0 || EPI == 1 || EPI == 3 || EPI == 5) {
                    float2 o; o.x = vx; o.y = vy;
                    *reinterpret_cast<float2*>(C + off) = o;
                }
                if (EPI == 2 || EPI == 4 || EPI == 5) {
                    f16 h0, l0, h1, l1;
                    split1(vx, h0, l0); split1(vy, h1, l1);
                    f162 hp; hp.x = h0; hp.y = h1;
                    f162 lp; lp.x = l0; lp.y = l1;
                    *reinterpret_cast<f162*>(Ch + off) = hp;
                    *reinterpret_cast<f162*>(Cl + off) = lp;
                }
            }
}

// ---------------- fp32 -> hi/lo fp16 split ---------------------------------
__global__ __launch_bounds__(256)
void split_f32(const float* __restrict__ in, f16* __restrict__ oh, f16* __restrict__ ol)
{
    const long i4 = (long)(blockIdx.x * 256 + threadIdx.x) * 4;
    const float4 v = *reinterpret_cast<const float4*>(in + i4);
    f16 h0, l0, h1, l1, h2, l2, h3, l3;
    split1(v.x, h0, l0); split1(v.y, h1, l1); split1(v.z, h2, l2); split1(v.w, h3, l3);
    f162 a; a.x = h0; a.y = h1;  f162 b; b.x = h2; b.y = h3;
    f162 c; c.x = l0; c.y = l1;  f162 d; d.x = l2; d.y = l3;
    *reinterpret_cast<f162*>(oh + i4)     = a;
    *reinterpret_cast<f162*>(oh + i4 + 2) = b;
    *reinterpret_cast<f162*>(ol + i4)     = c;
    *reinterpret_cast<f162*>(ol + i4 + 2) = d;
}

// ---------------- transpose + split: out[c][r] = in[r][c] -------------------
__global__ __launch_bounds__(256)
void transpose_split(const float* __restrict__ in, f16* __restrict__ oh, f16* __restrict__ ol,
                     int R, int Cc, long sIn, long sOut)
{
    __shared__ float tile[32][33];
    const int b = blockIdx.z;
    const int col0 = blockIdx.x * 32, row0 = blockIdx.y * 32;
    const int tx = threadIdx.x, ty = threadIdx.y;
    #pragma unroll
    for (int i = 0; i < 4; i++) {
        const int lr = ty + i * 8;
        tile[lr][tx] = in[(long)b * sIn + (long)(row0 + lr) * Cc + col0 + tx];
    }
    __syncthreads();
    #pragma unroll
    for (int i = 0; i < 4; i++) {
        const int lc = ty + i * 8;
        const float v = tile[tx][lc];
        f16 h, l; split1(v, h, l);
        const long o = (long)b * sOut + (long)(col0 + lc) * R + row0 + tx;
        oh[o] = h; ol[o] = l;
    }
}

// ---------------- weffT[j][d] = sum_h wout[h*D+d][j], split -----------------
__global__ __launch_bounds__(256)
void reduce_weffT(const float* __restrict__ wout, f16* __restrict__ oh, f16* __restrict__ ol)
{
    __shared__ float tile[32][33];
    const int j0 = blockIdx.x * 32, d0 = blockIdx.y * 32;
    const int tx = threadIdx.x, ty = threadIdx.y;
    #pragma unroll
    for (int i = 0; i < 4; i++) {
        const int ld = ty + i * 8;
        float s = 0.f;
        #pragma unroll
        for (int h = 0; h < HEADS; h++)
            s += wout[(long)h * DIM * DIM + (long)(d0 + ld) * DIM + j0 + tx];
        tile[ld][tx] = s;
    }
    __syncthreads();
    #pragma unroll
    for (int i = 0; i < 4; i++) {
        const int lj = ty + i * 8;
        const float v = tile[tx][lj];
        f16 h, l; split1(v, h, l);
        const long o = (long)(j0 + lj) * DIM + d0 + tx;
        oh[o] = h; ol[o] = l;
    }
}

// ---------------- causal softmax: fp32 scores -> split P --------------------
__global__ __launch_bounds__(256)
void softmax_split(float* __restrict__ sc, f16* __restrict__ ph, f16* __restrict__ pl, int S)
{
    const int gr = blockIdx.x;
    const int b = gr / S, i = gr % S;
    float* row = sc + (long)b * S * S + (long)i * S;
    f16* rh = ph + (long)b * S * S + (long)i * S;
    f16* rl = pl + (long)b * S * S + (long)i * S;
    const int n = i + 1;
    const int tid = threadIdx.x;
    __shared__ float red[256];

    float m = -3.0e38f;
    for (int j = tid; j < n; j += 256) m = fmaxf(m, row[j]);
    red[tid] = m; __syncthreads();
    for (int s = 128; s > 0; s >>= 1) { if (tid < s) red[tid] = fmaxf(red[tid], red[tid + s]); __syncthreads(); }
    m = red[0]; __syncthreads();

    float sum = 0.f;
    for (int j = tid; j < n; j += 256) { const float e = __expf(row[j] - m); row[j] = e; sum += e; }
    red[tid] = sum; __syncthreads();
    for (int s = 128; s > 0; s >>= 1) { if (tid < s) red[tid] += red[tid + s]; __syncthreads(); }
    const float inv = 1.f / red[0];

    for (int j = tid; j < n; j += 256) {
        const float p = row[j] * inv;
        f16 h, l; split1(p, h, l);
        rh[j] = h; rl[j] = l;
    }
    const f16 z = __float2half(0.f);
    for (int j = n + tid; j < S; j += 256) { rh[j] = z; rl[j] = z; }
}

// ---------------- LayerNorm -> split ----------------------------------------
__global__ __launch_bounds__(256)
void layernorm_split(const float* __restrict__ in, f16* __restrict__ oh, f16* __restrict__ ol, int N)
{
    const long r = blockIdx.x;
    const float* x = in + r * N;
    const int tid = threadIdx.x;
    __shared__ float rs[256], rss[256];

    const float4 a = *reinterpret_cast<const float4*>(&x[tid * 4]);
    rs[tid]  = a.x + a.y + a.z + a.w;
    rss[tid] = a.x * a.x + a.y * a.y + a.z * a.z + a.w * a.w;
    __syncthreads();
    for (int k = 128; k > 0; k >>= 1) {
        if (tid < k) { rs[tid] += rs[tid + k]; rss[tid] += rss[tid + k]; }
        __syncthreads();
    }
    const float mean = rs[0] / N;
    const float msq  = rss[0] / N;
    const float rstd = rsqrtf(msq - mean * mean + EPSLN);
    const float v0 = (a.x - mean) * rstd, v1 = (a.y - mean) * rstd;
    const float v2 = (a.z - mean) * rstd, v3 = (a.w - mean) * rstd;
    f16 h0, l0, h1, l1, h2, l2, h3, l3;
    split1(v0, h0, l0); split1(v1, h1, l1); split1(v2, h2, l2); split1(v3, h3, l3);
    f162 p0; p0.x = h0; p0.y = h1;
    f162 p1; p1.x = h2; p1.y = h3;
    f162 q0; q0.x = l0; q0.y = l1;
    f162 q1; q1.x = l2; q1.y = l3;
    *reinterpret_cast<f162*>(oh + r * N + tid * 4)     = p0;
    *reinterpret_cast<f162*>(oh + r * N + tid * 4 + 2) = p1;
    *reinterpret_cast<f162*>(ol + r * N + tid * 4)     = q0;
    *reinterpret_cast<f162*>(ol + r * N + tid * 4 + 2) = q1;
}

// ---------------------------------------------------------------------------
extern "C" void kernel_launch(void* const* d_in, const int* in_sizes, int n_in,
                              void* d_out, int out_size)
{
    const float* x    = (const float*)d_in[0];
    const float* wi   = (const float*)d_in[2];
    const float* wout = (const float*)d_in[3];
    const float* bias = (const float*)d_in[4];
    float* out = (float*)d_out;

    float *q, *sc, *h;
    f16 *xh, *xl, *qh, *ql, *qTh, *qTl, *ph, *pl, *hdh, *hdl, *hh, *hl, *th, *tl;
    f16 *wiTh, *wiTl, *weTh, *weTl;
    cudaGetSymbolAddress((void**)&q, g_q);     cudaGetSymbolAddress((void**)&sc, g_sc);
    cudaGetSymbolAddress((void**)&h, g_h);
    cudaGetSymbolAddress((void**)&xh, g_xh);   cudaGetSymbolAddress((void**)&xl, g_xl);
    cudaGetSymbolAddress((void**)&qh, g_qh);   cudaGetSymbolAddress((void**)&ql, g_ql);
    cudaGetSymbolAddress((void**)&qTh, g_qTh); cudaGetSymbolAddress((void**)&qTl, g_qTl);
    cudaGetSymbolAddress((void**)&ph, g_ph);   cudaGetSymbolAddress((void**)&pl, g_pl);
    cudaGetSymbolAddress((void**)&hdh, g_hdh); cudaGetSymbolAddress((void**)&hdl, g_hdl);
    cudaGetSymbolAddress((void**)&hh, g_hh);   cudaGetSymbolAddress((void**)&hl, g_hl);
    cudaGetSymbolAddress((void**)&th, g_th);   cudaGetSymbolAddress((void**)&tl, g_tl);
    cudaGetSymbolAddress((void**)&wiTh, g_wiTh); cudaGetSymbolAddress((void**)&wiTl, g_wiTl);
    cudaGetSymbolAddress((void**)&weTh, g_weTh); cudaGetSymbolAddress((void**)&weTl, g_weTl);

    cudaFuncSetAttribute(hmma_gemm<5,0,2>, cudaFuncAttributeMaxDynamicSharedMemorySize, GEMM_SMEM);
    cudaFuncSetAttribute(hmma_gemm<1,1,3>, cudaFuncAttributeMaxDynamicSharedMemorySize, GEMM_SMEM);
    cudaFuncSetAttribute(hmma_gemm<2,2,3>, cudaFuncAttributeMaxDynamicSharedMemorySize, GEMM_SMEM);
    cudaFuncSetAttribute(hmma_gemm<3,0,2>, cudaFuncAttributeMaxDynamicSharedMemorySize, GEMM_SMEM);
    cudaFuncSetAttribute(hmma_gemm<4,0,2>, cudaFuncAttributeMaxDynamicSharedMemorySize, GEMM_SMEM);
    cudaFuncSetAttribute(hmma_gemm<0,0,2>, cudaFuncAttributeMaxDynamicSharedMemorySize, GEMM_SMEM);

    const int S = SEQ, D = DIM, M = MROWS;
    const float alpha = 1.0f / 32.0f;   // 1/sqrt(1024)
    const long SD = (long)S * D, SS = (long)S * S;

    // prep: weight transposes/splits + x split
    reduce_weffT<<<dim3(32, 32, 1), dim3(32, 8)>>>(wout, weTh, weTl);
    transpose_split<<<dim3(32, 32, 1), dim3(32, 8)>>>(wi, wiTh, wiTl, D, D, 0, 0);
    split_f32<<<M * D / 1024, 256>>>(x, xh, xl);

    // q = x @ wi  (fp32 + splits; 2-pass)
    hmma_gemm<5,0,2><<<dim3(D/BNN, M/BMM, 1), 256, GEMM_SMEM>>>(
        xh, xl, wiTh, wiTl, q, qh, ql, nullptr, nullptr, M, D, D, 0.f, 0, 0, 0);

    // qT splits (per batch)
    transpose_split<<<dim3(D/32, S/32, BATCH), dim3(32, 8)>>>(q, qTh, qTl, S, D, SD, SD);

    // scores = alpha * q q^T  (causal tiles only; 3-pass)
    hmma_gemm<1,1,3><<<dim3(S/BNN, S/BMM, BATCH), 256, GEMM_SMEM>>>(
        qh, ql, qh, ql, sc, nullptr, nullptr, nullptr, nullptr, S, S, D, alpha, SD, SD, SS);

    // softmax -> P splits
    softmax_split<<<BATCH * S, 256>>>(sc, ph, pl, S);

    // head = P @ q + q  (splits out; K clamped causally; 3-pass)
    hmma_gemm<2,2,3><<<dim3(D/BNN, S/BMM, BATCH), 256, GEMM_SMEM>>>(
        ph, pl, qTh, qTl, nullptr, hdh, hdl, q, nullptr, S, D, S, 0.f, SS, SD, SD);

    // h = head @ W_eff + bias  (fp32; 2-pass)
    hmma_gemm<3,0,2><<<dim3(D/BNN, M/BMM, 1), 256, GEMM_SMEM>>>(
        hdh, hdl, weTh, weTl, h, nullptr, nullptr, nullptr, bias, M, D, D, 0.f, 0, 0, 0);

    // LayerNorm -> splits
    layernorm_split<<<M, 256>>>(h, hh, hl, D);

    // t = swish(h @ wi)  (splits out; 2-pass)
    hmma_gemm<4,0,2><<<dim3(D/BNN, M/BMM, 1), 256, GEMM_SMEM>>>(
        hh, hl, wiTh, wiTl, nullptr, th, tl, nullptr, nullptr, M, D, D, 0.f, 0, 0, 0);

    // out = t @ wi  (fp32; 2-pass)
    hmma_gemm<0,0,2><<<dim3(D/BNN, M/BMM, 1), 256, GEMM_SMEM>>>(
        th, tl, wiTh, wiTl, out, nullptr, nullptr, nullptr, nullptr, M, D, D, 0.f, 0, 0, 0);
}

// round 13
// speedup vs baseline: 2.4502x; 1.3163x over previous
#include <cuda_runtime.h>
#include <cuda_fp16.h>
#include <cstdint>
#include <math.h>

#define BATCH 2
#define SEQ   2048
#define DIM   1024
#define HEADS 8
#define MROWS (BATCH*SEQ)
#define EPSLN 1e-5f

typedef __half  f16;
typedef __half2 f162;

// ---------------- scratch (device globals; no allocation allowed) ----------
__device__ float g_q [MROWS*DIM];
__device__ float g_sc[BATCH*SEQ*SEQ];
__device__ float g_h [MROWS*DIM];
__device__ f16 g_xh [MROWS*DIM], g_xl [MROWS*DIM];
__device__ f16 g_qh [MROWS*DIM];
__device__ f16 g_qTh[MROWS*DIM];                     // [B][D][S]
__device__ f16 g_ph [BATCH*SEQ*SEQ];
__device__ f16 g_hdh[MROWS*DIM], g_hdl[MROWS*DIM];
__device__ f16 g_hh [MROWS*DIM], g_hl [MROWS*DIM];
__device__ f16 g_th [MROWS*DIM], g_tl [MROWS*DIM];
__device__ f16 g_wiTh[DIM*DIM];
__device__ f16 g_weTh[DIM*DIM];

// ---------------- PTX helpers ----------------------------------------------
__device__ __forceinline__ uint32_t smem_u32(const void* p) {
    uint32_t a;
    asm("{ .reg .u64 t; cvta.to.shared.u64 t, %1; cvt.u32.u64 %0, t; }" : "=r"(a) : "l"(p));
    return a;
}
__device__ __forceinline__ void ldsm4(uint32_t& r0, uint32_t& r1, uint32_t& r2, uint32_t& r3,
                                      uint32_t addr) {
    asm volatile("ldmatrix.sync.aligned.m8n8.x4.shared.b16 {%0,%1,%2,%3}, [%4];"
                 : "=r"(r0), "=r"(r1), "=r"(r2), "=r"(r3) : "r"(addr));
}
__device__ __forceinline__ void mma16816(float* d, const uint32_t* a, const uint32_t* b) {
    asm volatile(
        "mma.sync.aligned.m16n8k16.row.col.f32.f16.f16.f32 "
        "{%0,%1,%2,%3}, {%4,%5,%6,%7}, {%8,%9}, {%0,%1,%2,%3};"
        : "+f"(d[0]), "+f"(d[1]), "+f"(d[2]), "+f"(d[3])
        : "r"(a[0]), "r"(a[1]), "r"(a[2]), "r"(a[3]), "r"(b[0]), "r"(b[1]));
}
__device__ __forceinline__ void cp16(uint32_t dst, const void* src) {
    asm volatile("cp.async.cg.shared.global [%0], [%1], 16;" :: "r"(dst), "l"(src));
}
#define CP_COMMIT() asm volatile("cp.async.commit_group;" ::: "memory")
#define CP_WAIT1()  asm volatile("cp.async.wait_group 1;" ::: "memory")

__device__ __forceinline__ void split1(float v, f16& h, f16& l) {
    h = __float2half(v);
    l = __float2half(v - __half2float(h));
}

// ---------------- HMMA fp16-split GEMM --------------------------------------
// C[M,N](fp32) = A[M,K] * B^T.
// NPASS==1: AhBh                 (both operands single fp16)
// NPASS==2: AhBh + AlBh          (A split, B single)
// NPASS==3: AhBh + AlBh + AhBl   (both split)
#define BMM 128
#define BNN 128
#define BKK 64
#define KPAD 72                       // elements per smem row (64 + 8 pad)
#define ROWB (KPAD*2)                 // 144 bytes per row
#define ABYTES (128*ROWB)             // 18432 per buffer
#define STAGE  (4*ABYTES)             // Ah,Al,Bh,Bl = 73728
#define NSTAGE 3
#define GEMM_SMEM (NSTAGE*STAGE)      // 221184

// EPI: 0 fp32 | 1 alpha*fp32 | 2 res-add + split | 3 +bias fp32
//      4 swish+split | 5 fp32+split | 6 fp32 + hi-only split
// CAUSAL: 0 none | 1 skip tiles above diagonal | 2 clamp K to crow+BMM
template<int EPI, int CAUSAL, int NPASS>
__global__ __launch_bounds__(256, 1)
void hmma_gemm(const f16* __restrict__ Ah, const f16* __restrict__ Al,
               const f16* __restrict__ Bh, const f16* __restrict__ Bl,
               float* __restrict__ C, f16* __restrict__ Ch, f16* __restrict__ Cl,
               const float* __restrict__ res, const float* __restrict__ bias,
               int M, int N, int K, float alpha, long sA, long sB, long sC)
{
    const int crow = blockIdx.y * BMM;
    const int ccol = blockIdx.x * BNN;
    if (CAUSAL == 1 && ccol >= crow + BMM) return;

    const int b = blockIdx.z;
    Ah += (long)b * sA;
    if (NPASS >= 2) Al += (long)b * sA;
    Bh += (long)b * sB;
    if (NPASS == 3) Bl += (long)b * sB;

    extern __shared__ char smem[];
    const uint32_t sb = smem_u32(smem);
    const int tid  = threadIdx.x;
    const int lane = tid & 31;
    const int wid  = tid >> 5;
    const int wm   = wid & 1;        // 2 m-slices of 64
    const int wn   = wid >> 1;       // 4 n-slices of 32

    const int Keff = (CAUSAL == 2) ? (crow + BMM) : K;
    const int nC = Keff / BKK;

    // cp.async mapping: thread -> (row, 4 contiguous 16B chunks)
    const int r  = tid >> 1;
    const int c0 = (tid & 1) * 4;
    const f16* pAh = Ah + (long)(crow + r) * K + c0 * 8;
    const f16* pAl = (NPASS >= 2) ? (Al + (long)(crow + r) * K + c0 * 8) : nullptr;
    const f16* pBh = Bh + (long)(ccol + r) * K + c0 * 8;
    const f16* pBl = (NPASS == 3) ? (Bl + (long)(ccol + r) * K + c0 * 8) : nullptr;
    const uint32_t dstoff = r * ROWB + c0 * 16;

    // ldmatrix per-thread base addresses
    const uint32_t aAddr = sb + (wm * 64 + (lane & 15)) * ROWB + (lane >> 4) * 16;
    const uint32_t bAddr = sb + 2 * ABYTES +
                           (wn * 32 + ((lane >> 4) << 3) + (lane & 7)) * ROWB +
                           ((lane >> 3) & 1) * 16;

    float acc[4][4][4];
    #pragma unroll
    for (int i = 0; i < 4; i++)
        #pragma unroll
        for (int j = 0; j < 4; j++)
            #pragma unroll
            for (int k = 0; k < 4; k++) acc[i][j][k] = 0.f;

    // prologue: prefetch chunks 0 and 1 into stages 0, 1
    #pragma unroll
    for (int pc = 0; pc < 2; pc++) {
        if (pc < nC) {
            const uint32_t st = sb + pc * STAGE + dstoff;
            const long ke = (long)pc * BKK;
            #pragma unroll
            for (int i = 0; i < 4; i++) {
                cp16(st + i * 16,                              pAh + ke + i * 8);
                if (NPASS >= 2) cp16(st + ABYTES + i * 16,     pAl + ke + i * 8);
                cp16(st + 2 * ABYTES + i * 16,                 pBh + ke + i * 8);
                if (NPASS == 3) cp16(st + 3 * ABYTES + i * 16, pBl + ke + i * 8);
            }
        }
        CP_COMMIT();
    }

    uint32_t ah[2][4][4], al[2][4][4], bh[2][4][2], bl[2][4][2];

#define LOAD_FRAGS(buf, stg, kss) do {                                          \
    _Pragma("unroll")                                                           \
    for (int mt = 0; mt < 4; mt++) {                                            \
        const uint32_t ad = aAddr + (stg) + mt * (16 * ROWB) + (kss) * 32;      \
        ldsm4(ah[buf][mt][0], ah[buf][mt][1], ah[buf][mt][2], ah[buf][mt][3], ad); \
        if (NPASS >= 2)                                                         \
            ldsm4(al[buf][mt][0], al[buf][mt][1], al[buf][mt][2], al[buf][mt][3], ad + ABYTES); \
    }                                                                           \
    _Pragma("unroll")                                                           \
    for (int pr = 0; pr < 2; pr++) {                                            \
        const uint32_t bd = bAddr + (stg) + pr * (16 * ROWB) + (kss) * 32;      \
        uint32_t r0, r1, r2, r3;                                                \
        ldsm4(r0, r1, r2, r3, bd);                                              \
        bh[buf][2*pr][0] = r0; bh[buf][2*pr][1] = r1;                           \
        bh[buf][2*pr+1][0] = r2; bh[buf][2*pr+1][1] = r3;                       \
        if (NPASS == 3) {                                                       \
            ldsm4(r0, r1, r2, r3, bd + ABYTES);                                 \
            bl[buf][2*pr][0] = r0; bl[buf][2*pr][1] = r1;                       \
            bl[buf][2*pr+1][0] = r2; bl[buf][2*pr+1][1] = r3;                   \
        }                                                                       \
    }                                                                           \
} while (0)

    for (int c = 0; c < nC; c++) {
        CP_WAIT1();
        __syncthreads();

        if (c + 2 < nC) {
            const uint32_t st = sb + ((c + 2) % NSTAGE) * STAGE + dstoff;
            const long ke = (long)(c + 2) * BKK;
            #pragma unroll
            for (int i = 0; i < 4; i++) {
                cp16(st + i * 16,                              pAh + ke + i * 8);
                if (NPASS >= 2) cp16(st + ABYTES + i * 16,     pAl + ke + i * 8);
                cp16(st + 2 * ABYTES + i * 16,                 pBh + ke + i * 8);
                if (NPASS == 3) cp16(st + 3 * ABYTES + i * 16, pBl + ke + i * 8);
            }
        }
        CP_COMMIT();

        const uint32_t stg = (c % NSTAGE) * STAGE;
        LOAD_FRAGS(0, stg, 0);
        #pragma unroll
        for (int ks = 0; ks < 4; ks++) {
            const int cur = ks & 1;
            if (ks < 3) LOAD_FRAGS(cur ^ 1, stg, ks + 1);
            #pragma unroll
            for (int mt = 0; mt < 4; mt++)
                #pragma unroll
                for (int nt = 0; nt < 4; nt++)
                    mma16816(acc[mt][nt], ah[cur][mt], bh[cur][nt]);
            if (NPASS >= 2) {
                #pragma unroll
                for (int mt = 0; mt < 4; mt++)
                    #pragma unroll
                    for (int nt = 0; nt < 4; nt++)
                        mma16816(acc[mt][nt], al[cur][mt], bh[cur][nt]);
            }
            if (NPASS == 3) {
                #pragma unroll
                for (int mt = 0; mt < 4; mt++)
                    #pragma unroll
                    for (int nt = 0; nt < 4; nt++)
                        mma16816(acc[mt][nt], ah[cur][mt], bl[cur][nt]);
            }
        }
    }
#undef LOAD_FRAGS

    // ---------------- epilogue ----------------
    const int g  = lane >> 2;
    const int tg = lane & 3;
    #pragma unroll
    for (int mt = 0; mt < 4; mt++)
        #pragma unroll
        for (int nt = 0; nt < 4; nt++)
            #pragma unroll
            for (int hh = 0; hh < 2; hh++) {
                const int row = crow + wm * 64 + mt * 16 + g + hh * 8;
                const int col = ccol + wn * 32 + nt * 8 + tg * 2;
                const long off = (long)b * sC + (long)row * N + col;
                float vx = acc[mt][nt][hh * 2 + 0];
                float vy = acc[mt][nt][hh * 2 + 1];
                if (EPI == 1) { vx *= alpha; vy *= alpha; }
                if (EPI == 2) {
                    const float2 r2 = *reinterpret_cast<const float2*>(res + off);
                    vx += r2.x; vy += r2.y;
                }
                if (EPI == 3) { vx += bias[col]; vy += bias[col + 1]; }
                if (EPI == 4) {
                    vx = vx / (1.f + __expf(-vx));
                    vy = vy / (1.f + __expf(-vy));
                }
                if (EPI == 0 || EPI == 1 || EPI == 3 || EPI == 5 || EPI == 6) {
                    float2 o; o.x = vx; o.y = vy;
                    *reinterpret_cast<float2*>(C + off) = o;
                }
                if (EPI == 2 || EPI == 4 || EPI == 5) {
                    f16 h0, l0, h1, l1;
                    split1(vx, h0, l0); split1(vy, h1, l1);
                    f162 hp; hp.x = h0; hp.y = h1;
                    f162 lp; lp.x = l0; lp.y = l1;
                    *reinterpret_cast<f162*>(Ch + off) = hp;
                    *reinterpret_cast<f162*>(Cl + off) = lp;
                }
                if (EPI == 6) {
                    f162 hp; hp.x = __float2half(vx); hp.y = __float2half(vy);
                    *reinterpret_cast<f162*>(Ch + off) = hp;
                }
            }
}

// ---------------- fp32 -> hi/lo fp16 split ---------------------------------
__global__ __launch_bounds__(256)
void split_f32(const float* __restrict__ in, f16* __restrict__ oh, f16* __restrict__ ol)
{
    const long i4 = (long)(blockIdx.x * 256 + threadIdx.x) * 4;
    const float4 v = *reinterpret_cast<const float4*>(in + i4);
    f16 h0, l0, h1, l1, h2, l2, h3, l3;
    split1(v.x, h0, l0); split1(v.y, h1, l1); split1(v.z, h2, l2); split1(v.w, h3, l3);
    f162 a; a.x = h0; a.y = h1;  f162 b; b.x = h2; b.y = h3;
    f162 c; c.x = l0; c.y = l1;  f162 d; d.x = l2; d.y = l3;
    *reinterpret_cast<f162*>(oh + i4)     = a;
    *reinterpret_cast<f162*>(oh + i4 + 2) = b;
    *reinterpret_cast<f162*>(ol + i4)     = c;
    *reinterpret_cast<f162*>(ol + i4 + 2) = d;
}

// ---------------- transpose (+optional lo): out[c][r] = in[r][c] ------------
__global__ __launch_bounds__(256)
void transpose_split(const float* __restrict__ in, f16* __restrict__ oh, f16* __restrict__ ol,
                     int R, int Cc, long sIn, long sOut)
{
    __shared__ float tile[32][33];
    const int b = blockIdx.z;
    const int col0 = blockIdx.x * 32, row0 = blockIdx.y * 32;
    const int tx = threadIdx.x, ty = threadIdx.y;
    #pragma unroll
    for (int i = 0; i < 4; i++) {
        const int lr = ty + i * 8;
        tile[lr][tx] = in[(long)b * sIn + (long)(row0 + lr) * Cc + col0 + tx];
    }
    __syncthreads();
    #pragma unroll
    for (int i = 0; i < 4; i++) {
        const int lc = ty + i * 8;
        const float v = tile[tx][lc];
        const long o = (long)b * sOut + (long)(col0 + lc) * R + row0 + tx;
        f16 h, l; split1(v, h, l);
        oh[o] = h;
        if (ol) ol[o] = l;
    }
}

// ---------------- weffT[j][d] = sum_h wout[h*D+d][j], hi only ---------------
__global__ __launch_bounds__(256)
void reduce_weffT(const float* __restrict__ wout, f16* __restrict__ oh)
{
    __shared__ float tile[32][33];
    const int j0 = blockIdx.x * 32, d0 = blockIdx.y * 32;
    const int tx = threadIdx.x, ty = threadIdx.y;
    #pragma unroll
    for (int i = 0; i < 4; i++) {
        const int ld = ty + i * 8;
        float s = 0.f;
        #pragma unroll
        for (int h = 0; h < HEADS; h++)
            s += wout[(long)h * DIM * DIM + (long)(d0 + ld) * DIM + j0 + tx];
        tile[ld][tx] = s;
    }
    __syncthreads();
    #pragma unroll
    for (int i = 0; i < 4; i++) {
        const int lj = ty + i * 8;
        oh[(long)(j0 + lj) * DIM + d0 + tx] = __float2half(tile[tx][lj]);
    }
}

// ---------------- causal softmax: fp32 scores -> fp16 P (hi only) ----------
__global__ __launch_bounds__(256)
void softmax_f16(float* __restrict__ sc, f16* __restrict__ ph, int S)
{
    const int gr = blockIdx.x;
    const int b = gr / S, i = gr % S;
    float* row = sc + (long)b * S * S + (long)i * S;
    f16* rh = ph + (long)b * S * S + (long)i * S;
    const int n = i + 1;
    const int tid = threadIdx.x;
    __shared__ float red[256];

    float m = -3.0e38f;
    for (int j = tid; j < n; j += 256) m = fmaxf(m, row[j]);
    red[tid] = m; __syncthreads();
    for (int s = 128; s > 0; s >>= 1) { if (tid < s) red[tid] = fmaxf(red[tid], red[tid + s]); __syncthreads(); }
    m = red[0]; __syncthreads();

    float sum = 0.f;
    for (int j = tid; j < n; j += 256) { const float e = __expf(row[j] - m); row[j] = e; sum += e; }
    red[tid] = sum; __syncthreads();
    for (int s = 128; s > 0; s >>= 1) { if (tid < s) red[tid] += red[tid + s]; __syncthreads(); }
    const float inv = 1.f / red[0];

    for (int j = tid; j < n; j += 256) rh[j] = __float2half(row[j] * inv);
    const f16 z = __float2half(0.f);
    for (int j = n + tid; j < S; j += 256) rh[j] = z;
}

// ---------------- LayerNorm -> split ----------------------------------------
__global__ __launch_bounds__(256)
void layernorm_split(const float* __restrict__ in, f16* __restrict__ oh, f16* __restrict__ ol, int N)
{
    const long r = blockIdx.x;
    const float* x = in + r * N;
    const int tid = threadIdx.x;
    __shared__ float rs[256], rss[256];

    const float4 a = *reinterpret_cast<const float4*>(&x[tid * 4]);
    rs[tid]  = a.x + a.y + a.z + a.w;
    rss[tid] = a.x * a.x + a.y * a.y + a.z * a.z + a.w * a.w;
    __syncthreads();
    for (int k = 128; k > 0; k >>= 1) {
        if (tid < k) { rs[tid] += rs[tid + k]; rss[tid] += rss[tid + k]; }
        __syncthreads();
    }
    const float mean = rs[0] / N;
    const float msq  = rss[0] / N;
    const float rstd = rsqrtf(msq - mean * mean + EPSLN);
    const float v0 = (a.x - mean) * rstd, v1 = (a.y - mean) * rstd;
    const float v2 = (a.z - mean) * rstd, v3 = (a.w - mean) * rstd;
    f16 h0, l0, h1, l1, h2, l2, h3, l3;
    split1(v0, h0, l0); split1(v1, h1, l1); split1(v2, h2, l2); split1(v3, h3, l3);
    f162 p0; p0.x = h0; p0.y = h1;
    f162 p1; p1.x = h2; p1.y = h3;
    f162 q0; q0.x = l0; q0.y = l1;
    f162 q1; q1.x = l2; q1.y = l3;
    *reinterpret_cast<f162*>(oh + r * N + tid * 4)     = p0;
    *reinterpret_cast<f162*>(oh + r * N + tid * 4 + 2) = p1;
    *reinterpret_cast<f162*>(ol + r * N + tid * 4)     = q0;
    *reinterpret_cast<f162*>(ol + r * N + tid * 4 + 2) = q1;
}

// ---------------------------------------------------------------------------
extern "C" void kernel_launch(void* const* d_in, const int* in_sizes, int n_in,
                              void* d_out, int out_size)
{
    const float* x    = (const float*)d_in[0];
    const float* wi   = (const float*)d_in[2];
    const float* wout = (const float*)d_in[3];
    const float* bias = (const float*)d_in[4];
    float* out = (float*)d_out;

    float *q, *sc, *h;
    f16 *xh, *xl, *qh, *qTh, *ph, *hdh, *hdl, *hh, *hl, *th, *tl, *wiTh, *weTh;
    cudaGetSymbolAddress((void**)&q, g_q);     cudaGetSymbolAddress((void**)&sc, g_sc);
    cudaGetSymbolAddress((void**)&h, g_h);
    cudaGetSymbolAddress((void**)&xh, g_xh);   cudaGetSymbolAddress((void**)&xl, g_xl);
    cudaGetSymbolAddress((void**)&qh, g_qh);
    cudaGetSymbolAddress((void**)&qTh, g_qTh);
    cudaGetSymbolAddress((void**)&ph, g_ph);
    cudaGetSymbolAddress((void**)&hdh, g_hdh); cudaGetSymbolAddress((void**)&hdl, g_hdl);
    cudaGetSymbolAddress((void**)&hh, g_hh);   cudaGetSymbolAddress((void**)&hl, g_hl);
    cudaGetSymbolAddress((void**)&th, g_th);   cudaGetSymbolAddress((void**)&tl, g_tl);
    cudaGetSymbolAddress((void**)&wiTh, g_wiTh);
    cudaGetSymbolAddress((void**)&weTh, g_weTh);

    cudaFuncSetAttribute(hmma_gemm<6,0,2>, cudaFuncAttributeMaxDynamicSharedMemorySize, GEMM_SMEM);
    cudaFuncSetAttribute(hmma_gemm<1,1,1>, cudaFuncAttributeMaxDynamicSharedMemorySize, GEMM_SMEM);
    cudaFuncSetAttribute(hmma_gemm<2,2,1>, cudaFuncAttributeMaxDynamicSharedMemorySize, GEMM_SMEM);
    cudaFuncSetAttribute(hmma_gemm<3,0,2>, cudaFuncAttributeMaxDynamicSharedMemorySize, GEMM_SMEM);
    cudaFuncSetAttribute(hmma_gemm<4,0,2>, cudaFuncAttributeMaxDynamicSharedMemorySize, GEMM_SMEM);
    cudaFuncSetAttribute(hmma_gemm<0,0,2>, cudaFuncAttributeMaxDynamicSharedMemorySize, GEMM_SMEM);

    const int S = SEQ, D = DIM, M = MROWS;
    const float alpha = 1.0f / 32.0f;   // 1/sqrt(1024)
    const long SD = (long)S * D, SS = (long)S * S;

    // prep: weight transposes/splits + x split
    reduce_weffT<<<dim3(32, 32, 1), dim3(32, 8)>>>(wout, weTh);
    transpose_split<<<dim3(32, 32, 1), dim3(32, 8)>>>(wi, wiTh, nullptr, D, D, 0, 0);
    split_f32<<<M * D / 1024, 256>>>(x, xh, xl);

    // q = x @ wi  (fp32 + hi split; 2-pass)
    hmma_gemm<6,0,2><<<dim3(D/BNN, M/BMM, 1), 256, GEMM_SMEM>>>(
        xh, xl, wiTh, nullptr, q, qh, nullptr, nullptr, nullptr, M, D, D, 0.f, 0, 0, 0);

    // qT hi (per batch)
    transpose_split<<<dim3(D/32, S/32, BATCH), dim3(32, 8)>>>(q, qTh, nullptr, S, D, SD, SD);

    // scores = alpha * qh qh^T  (causal tiles only; 1-pass)
    hmma_gemm<1,1,1><<<dim3(S/BNN, S/BMM, BATCH), 256, GEMM_SMEM>>>(
        qh, nullptr, qh, nullptr, sc, nullptr, nullptr, nullptr, nullptr, S, S, D, alpha, SD, SD, SS);

    // softmax -> fp16 P (hi only)
    softmax_f16<<<BATCH * S, 256>>>(sc, ph, S);

    // head = P @ qh + q  (splits out; K clamped causally; 1-pass)
    hmma_gemm<2,2,1><<<dim3(D/BNN, S/BMM, BATCH), 256, GEMM_SMEM>>>(
        ph, nullptr, qTh, nullptr, nullptr, hdh, hdl, q, nullptr, S, D, S, 0.f, SS, SD, SD);

    // h = head @ W_eff + bias  (fp32; 2-pass)
    hmma_gemm<3,0,2><<<dim3(D/BNN, M/BMM, 1), 256, GEMM_SMEM>>>(
        hdh, hdl, weTh, nullptr, h, nullptr, nullptr, nullptr, bias, M, D, D, 0.f, 0, 0, 0);

    // LayerNorm -> splits
    layernorm_split<<<M, 256>>>(h, hh, hl, D);

    // t = swish(h @ wi)  (splits out; 2-pass)
    hmma_gemm<4,0,2><<<dim3(D/BNN, M/BMM, 1), 256, GEMM_SMEM>>>(
        hh, hl, wiTh, nullptr, nullptr, th, tl, nullptr, nullptr, M, D, D, 0.f, 0, 0, 0);

    // out = t @ wi  (fp32; 2-pass)
    hmma_gemm<0,0,2><<<dim3(D/BNN, M/BMM, 1), 256, GEMM_SMEM>>>(
        th, tl, wiTh, nullptr, out, nullptr, nullptr, nullptr, nullptr, M, D, D, 0.f, 0, 0, 0);
}